// round 2
// baseline (speedup 1.0000x reference)
#include <cuda_runtime.h>
#include <math.h>

#define BB 32
#define H0 256
#define W0 512
#define NT 256

// ---------------- scratch (static device globals; no runtime allocation) ----
__device__ float g_lp1[BB*3*128*256];
__device__ float g_rp1[BB*3*128*256];
__device__ float g_lp2[BB*3*64*128];
__device__ float g_rp2[BB*3*64*128];
__device__ float g_lp3[BB*3*32*64];
__device__ float g_rp3[BB*3*32*64];

__device__ float g_le0[BB*3*256*512];
__device__ float g_re0[BB*3*256*512];
__device__ float g_le1[BB*3*128*256];
__device__ float g_re1[BB*3*128*256];
__device__ float g_le2[BB*3*64*128];
__device__ float g_re2[BB*3*64*128];
__device__ float g_le3[BB*3*32*64];
__device__ float g_re3[BB*3*32*64];

// per level i, 8 slots: 0 dssim_l, 1 dssim_r, 2 l1_l, 3 l1_r, 4 lr_l, 5 lr_r, 6 ds_l, 7 ds_r
__device__ double g_acc[32];

// ---------------- reduction helper ----------------
template<int NV>
__device__ __forceinline__ void block_accumulate(float (&v)[NV], double* accs) {
    #pragma unroll
    for (int k = 0; k < NV; k++)
        #pragma unroll
        for (int o = 16; o > 0; o >>= 1)
            v[k] += __shfl_down_sync(0xffffffffu, v[k], o);
    __shared__ float sh[NV][8];
    int lane = threadIdx.x & 31, w = threadIdx.x >> 5;
    if (lane == 0) {
        #pragma unroll
        for (int k = 0; k < NV; k++) sh[k][w] = v[k];
    }
    __syncthreads();
    if (threadIdx.x == 0) {
        int nw = (blockDim.x + 31) >> 5;
        #pragma unroll
        for (int k = 0; k < NV; k++) {
            float s = 0.f;
            for (int i = 0; i < nw; i++) s += sh[k][i];
            atomicAdd(accs + k, (double)s);
        }
    }
}

__global__ void zero_acc_kernel() {
    if (threadIdx.x < 32) g_acc[threadIdx.x] = 0.0;
}

// ---------------- bilinear align-corners resize (one thread / output elem) ---
__global__ void resize_kernel(const float* __restrict__ src, float* __restrict__ dst,
                              int BC, int h, int w, int nh, int nw) {
    int idx = blockIdx.x * blockDim.x + threadIdx.x;
    int total = BC * nh * nw;
    if (idx >= total) return;
    int x  = idx % nw;
    int t  = idx / nw;
    int y  = t % nh;
    int bc = t / nh;
    float fy = (float)y * (float)(h - 1) / (float)(nh - 1);
    float fx = (float)x * (float)(w - 1) / (float)(nw - 1);
    int y0 = (int)floorf(fy); int y1 = min(y0 + 1, h - 1);
    int x0 = (int)floorf(fx); int x1 = min(x0 + 1, w - 1);
    float wy = fy - (float)y0, wx = fx - (float)x0;
    const float* s = src + (size_t)bc * h * w;
    float top = s[(size_t)y0 * w + x0] * (1.f - wx) + s[(size_t)y0 * w + x1] * wx;
    float bot = s[(size_t)y1 * w + x0] * (1.f - wx) + s[(size_t)y1 * w + x1] * wx;
    dst[idx] = top * (1.f - wy) + bot * wy;
}

// ---------------- fused warp + L1 + LR-consistency ----------------
// left_est = warp_x(rp, x - dl*(W-1)); right_est = warp_x(lp, x + dr*(W-1))
// r2l = warp_x(dr, x - dl*(W-1)); l2r = warp_x(dl, x + dr*(W-1))
__global__ void warp_kernel(const float* __restrict__ lp, const float* __restrict__ rp,
                            const float* __restrict__ disp,
                            float* __restrict__ lest, float* __restrict__ rest,
                            int H, int W, double* accs /* base + level*8 */) {
    int idx = blockIdx.x * blockDim.x + threadIdx.x;
    int total = BB * H * W;
    float v[4] = {0.f, 0.f, 0.f, 0.f}; // l1_l, l1_r, lr_l, lr_r
    if (idx < total) {
        int x = idx % W;
        int t = idx / W;
        int y = t % H;
        int b = t / H;
        int plane = H * W;
        const float* dlrow = disp + (size_t)b * 2 * plane + (size_t)y * W;
        const float* drrow = dlrow + plane;
        float dlv = dlrow[x], drv = drrow[x];
        float scale = (float)(W - 1);
        float xl = (float)x - dlv * scale;
        float xr = (float)x + drv * scale;
        float xl0f = floorf(xl); int xl0 = (int)xl0f; float wl = xl - xl0f;
        float xr0f = floorf(xr); int xr0 = (int)xr0f; float wr = xr - xr0f;
        bool l0v = (xl0 >= 0) && (xl0 < W);
        bool l1v = (xl0 + 1 >= 0) && (xl0 + 1 < W);
        bool r0v = (xr0 >= 0) && (xr0 < W);
        bool r1v = (xr0 + 1 >= 0) && (xr0 + 1 < W);
        #pragma unroll
        for (int c = 0; c < 3; c++) {
            const float* lrow = lp + ((size_t)b * 3 + c) * plane + (size_t)y * W;
            const float* rrow = rp + ((size_t)b * 3 + c) * plane + (size_t)y * W;
            float le = (l0v ? rrow[xl0] : 0.f) * (1.f - wl) + (l1v ? rrow[xl0 + 1] : 0.f) * wl;
            float re = (r0v ? lrow[xr0] : 0.f) * (1.f - wr) + (r1v ? lrow[xr0 + 1] : 0.f) * wr;
            lest[((size_t)b * 3 + c) * plane + (size_t)y * W + x] = le;
            rest[((size_t)b * 3 + c) * plane + (size_t)y * W + x] = re;
            v[0] += fabsf(lrow[x] - le);
            v[1] += fabsf(rrow[x] - re);
        }
        float r2l = (l0v ? drrow[xl0] : 0.f) * (1.f - wl) + (l1v ? drrow[xl0 + 1] : 0.f) * wl;
        float l2r = (r0v ? dlrow[xr0] : 0.f) * (1.f - wr) + (r1v ? dlrow[xr0 + 1] : 0.f) * wr;
        v[2] = fabsf(dlv - r2l);
        v[3] = fabsf(drv - l2r);
    }
    block_accumulate<4>(v, accs + 2);
}

// ---------------- DSSIM (3x3 VALID windows, direct) ----------------
__global__ void dssim_kernel(const float* __restrict__ X, const float* __restrict__ Y,
                             int H, int W, double* acc1) {
    int oH = H - 2, oW = W - 2;
    int idx = blockIdx.x * blockDim.x + threadIdx.x;
    int total = BB * 3 * oH * oW;
    float v[1] = {0.f};
    if (idx < total) {
        int ox = idx % oW;
        int t  = idx / oW;
        int oy = t % oH;
        int bc = t / oH;
        const float* xb = X + (size_t)bc * H * W + (size_t)oy * W + ox;
        const float* yb = Y + (size_t)bc * H * W + (size_t)oy * W + ox;
        float sx = 0.f, sy = 0.f, sxx = 0.f, syy = 0.f, sxy = 0.f;
        #pragma unroll
        for (int j = 0; j < 3; j++) {
            #pragma unroll
            for (int i = 0; i < 3; i++) {
                float a = __ldg(xb + (size_t)j * W + i);
                float b = __ldg(yb + (size_t)j * W + i);
                sx += a; sy += b; sxx += a * a; syy += b * b; sxy += a * b;
            }
        }
        const float inv9 = 1.f / 9.f;
        float mux = sx * inv9, muy = sy * inv9;
        float sigx = sxx * inv9 - mux * mux;
        float sigy = syy * inv9 - muy * muy;
        float cov  = sxy * inv9 - mux * muy;
        const float C1 = 1e-4f, C2 = 9e-4f;
        float ssim = ((2.f * mux * muy + C1) * (2.f * cov + C2))
                   / ((mux * mux + muy * muy + C1) * (sigx + sigy + C2));
        v[0] = fminf(fmaxf((1.f - ssim) * 0.5f, 0.f), 1.f);
    }
    block_accumulate<1>(v, acc1);
}

// ---------------- fused edge-aware smoothness (both sides) ----------------
__global__ void smooth_kernel(const float* __restrict__ lp, const float* __restrict__ rp,
                              const float* __restrict__ disp,
                              int H, int W, double* accs /* -> ds_l, ds_r */) {
    int idx = blockIdx.x * blockDim.x + threadIdx.x;
    int total = BB * H * W;
    float v[2] = {0.f, 0.f};
    if (idx < total) {
        int x = idx % W;
        int t = idx / W;
        int y = t % H;
        int b = t / H;
        int plane = H * W;
        const float* dl = disp + (size_t)b * 2 * plane;
        const float* dr = dl + plane;
        int p = y * W + x;
        float dlv = dl[p], drv = dr[p];
        float vl = 0.f, vr = 0.f;
        if (x < W - 1) {
            float gl = 0.f, gr = 0.f;
            #pragma unroll
            for (int c = 0; c < 3; c++) {
                const float* li = lp + ((size_t)b * 3 + c) * plane;
                const float* ri = rp + ((size_t)b * 3 + c) * plane;
                gl += fabsf(li[p] - li[p + 1]);
                gr += fabsf(ri[p] - ri[p + 1]);
            }
            vl += fabsf((dlv - dl[p + 1]) * expf(-gl * (1.f / 3.f)));
            vr += fabsf((drv - dr[p + 1]) * expf(-gr * (1.f / 3.f)));
        }
        if (y < H - 1) {
            float gl = 0.f, gr = 0.f;
            #pragma unroll
            for (int c = 0; c < 3; c++) {
                const float* li = lp + ((size_t)b * 3 + c) * plane;
                const float* ri = rp + ((size_t)b * 3 + c) * plane;
                gl += fabsf(li[p] - li[p + W]);
                gr += fabsf(ri[p] - ri[p + W]);
            }
            vl += fabsf((dlv - dl[p + W]) * expf(-gl * (1.f / 3.f)));
            vr += fabsf((drv - dr[p + W]) * expf(-gr * (1.f / 3.f)));
        }
        v[0] = vl;
        v[1] = vr;
    }
    block_accumulate<2>(v, accs);
}

// ---------------- final combine ----------------
__global__ void final_kernel(float* __restrict__ out) {
    double AP = 0.0, LR = 0.0, DS = 0.0;
    for (int i = 0; i < 4; i++) {
        int Hi = H0 >> i, Wi = W0 >> i;
        double Nd = (double)BB * 3.0 * (Hi - 2) * (Wi - 2);
        double Nl = (double)BB * 3.0 * Hi * Wi;
        double Np = (double)BB * Hi * Wi;
        const double* a = g_acc + i * 8;
        AP += 0.85 * (a[0] + a[1]) / Nd + 0.15 * (a[2] + a[3]) / Nl;
        LR += (a[4] + a[5]) / Np;
        DS += (a[6] + a[7]) / Np / (double)(1 << i);
    }
    AP *= 0.85;
    DS *= 0.1;
    double total = AP + LR + DS;
    out[0] = (float)total;
    out[1] = (float)AP;
    out[2] = (float)LR;
    out[3] = (float)DS;
}

// ---------------- host launcher ----------------
extern "C" void kernel_launch(void* const* d_in, const int* in_sizes, int n_in,
                              void* d_out, int out_size) {
    const float* disp0 = (const float*)d_in[0];
    const float* disp1 = (const float*)d_in[1];
    const float* disp2 = (const float*)d_in[2];
    const float* disp3 = (const float*)d_in[3];
    const float* left  = (const float*)d_in[4];
    const float* right = (const float*)d_in[5];
    float* out = (float*)d_out;

    static bool init = false;
    static float *lp1, *rp1, *lp2, *rp2, *lp3, *rp3;
    static float *le0, *re0, *le1, *re1, *le2, *re2, *le3, *re3;
    static double* acc;
    if (!init) {
        cudaGetSymbolAddress((void**)&lp1, g_lp1);
        cudaGetSymbolAddress((void**)&rp1, g_rp1);
        cudaGetSymbolAddress((void**)&lp2, g_lp2);
        cudaGetSymbolAddress((void**)&rp2, g_rp2);
        cudaGetSymbolAddress((void**)&lp3, g_lp3);
        cudaGetSymbolAddress((void**)&rp3, g_rp3);
        cudaGetSymbolAddress((void**)&le0, g_le0);
        cudaGetSymbolAddress((void**)&re0, g_re0);
        cudaGetSymbolAddress((void**)&le1, g_le1);
        cudaGetSymbolAddress((void**)&re1, g_re1);
        cudaGetSymbolAddress((void**)&le2, g_le2);
        cudaGetSymbolAddress((void**)&re2, g_re2);
        cudaGetSymbolAddress((void**)&le3, g_le3);
        cudaGetSymbolAddress((void**)&re3, g_re3);
        cudaGetSymbolAddress((void**)&acc, g_acc);
        init = true;
    }

    zero_acc_kernel<<<1, 32>>>();

    const int BC = BB * 3;
    // pyramid chain (cascaded, as in reference)
    {
        int n1 = BC * 128 * 256;
        resize_kernel<<<(n1 + NT - 1) / NT, NT>>>(left,  lp1, BC, 256, 512, 128, 256);
        resize_kernel<<<(n1 + NT - 1) / NT, NT>>>(right, rp1, BC, 256, 512, 128, 256);
        int n2 = BC * 64 * 128;
        resize_kernel<<<(n2 + NT - 1) / NT, NT>>>(lp1, lp2, BC, 128, 256, 64, 128);
        resize_kernel<<<(n2 + NT - 1) / NT, NT>>>(rp1, rp2, BC, 128, 256, 64, 128);
        int n3 = BC * 32 * 64;
        resize_kernel<<<(n3 + NT - 1) / NT, NT>>>(lp2, lp3, BC, 64, 128, 32, 64);
        resize_kernel<<<(n3 + NT - 1) / NT, NT>>>(rp2, rp3, BC, 64, 128, 32, 64);
    }

    const float* lps[4]   = {left,  lp1, lp2, lp3};
    const float* rps[4]   = {right, rp1, rp2, rp3};
    const float* disps[4] = {disp0, disp1, disp2, disp3};
    float* lests[4] = {le0, le1, le2, le3};
    float* rests[4] = {re0, re1, re2, re3};
    int Hs[4] = {256, 128, 64, 32};
    int Ws[4] = {512, 256, 128, 64};

    for (int i = 0; i < 4; i++) {
        int H = Hs[i], W = Ws[i];
        int np = BB * H * W;
        warp_kernel<<<(np + NT - 1) / NT, NT>>>(lps[i], rps[i], disps[i],
                                                lests[i], rests[i], H, W, acc + i * 8);
        int nd = BB * 3 * (H - 2) * (W - 2);
        dssim_kernel<<<(nd + NT - 1) / NT, NT>>>(lps[i], lests[i], H, W, acc + i * 8 + 0);
        dssim_kernel<<<(nd + NT - 1) / NT, NT>>>(rps[i], rests[i], H, W, acc + i * 8 + 1);
        smooth_kernel<<<(np + NT - 1) / NT, NT>>>(lps[i], rps[i], disps[i], H, W, acc + i * 8 + 6);
    }

    final_kernel<<<1, 1>>>(out);
}

// round 3
// speedup vs baseline: 1.1207x; 1.1207x over previous
#include <cuda_runtime.h>
#include <math.h>

#define BB 32
#define H0 256
#define W0 512
#define NT 256

#define TX 32
#define TY 8
#define HTX (TX + 2)
#define HTY (TY + 2)
#define HN (HTX * HTY)

// ---------------- scratch ----------------
__device__ float g_lp1[BB*3*128*256];
__device__ float g_rp1[BB*3*128*256];
__device__ float g_lp2[BB*3*64*128];
__device__ float g_rp2[BB*3*64*128];
__device__ float g_lp3[BB*3*32*64];
__device__ float g_rp3[BB*3*32*64];

// per level i, 8 slots: 0 dssim_l, 1 dssim_r, 2 l1_l, 3 l1_r, 4 lr_l, 5 lr_r, 6 ds_l, 7 ds_r
__device__ double g_acc[32];

// ---------------- reduction helper ----------------
template<int NV>
__device__ __forceinline__ void block_accumulate(float (&v)[NV], double* accs) {
    #pragma unroll
    for (int k = 0; k < NV; k++)
        #pragma unroll
        for (int o = 16; o > 0; o >>= 1)
            v[k] += __shfl_down_sync(0xffffffffu, v[k], o);
    __shared__ float sh[NV][8];
    int lane = threadIdx.x & 31, w = threadIdx.x >> 5;
    if (lane == 0) {
        #pragma unroll
        for (int k = 0; k < NV; k++) sh[k][w] = v[k];
    }
    __syncthreads();
    if (threadIdx.x == 0) {
        int nw = (blockDim.x + 31) >> 5;
        #pragma unroll
        for (int k = 0; k < NV; k++) {
            float s = 0.f;
            for (int i = 0; i < nw; i++) s += sh[k][i];
            atomicAdd(accs + k, (double)s);
        }
    }
}

__global__ void zero_acc_kernel() {
    if (threadIdx.x < 32) g_acc[threadIdx.x] = 0.0;
}

// ---------------- paired bilinear align-corners resize ----------------
__global__ void resize2_kernel(const float* __restrict__ srcA, float* __restrict__ dstA,
                               const float* __restrict__ srcB, float* __restrict__ dstB,
                               int BC, int h, int w, int nh, int nw) {
    int idx = blockIdx.x * blockDim.x + threadIdx.x;
    int total = BC * nh * nw;
    int which = 0;
    if (idx >= total) { idx -= total; which = 1; if (idx >= total) return; }
    const float* src = which ? srcB : srcA;
    float* dst = which ? dstB : dstA;
    int x  = idx % nw;
    int t  = idx / nw;
    int y  = t % nh;
    int bc = t / nh;
    float fy = (float)y * (float)(h - 1) / (float)(nh - 1);
    float fx = (float)x * (float)(w - 1) / (float)(nw - 1);
    int y0 = (int)floorf(fy); int y1 = min(y0 + 1, h - 1);
    int x0 = (int)floorf(fx); int x1 = min(x0 + 1, w - 1);
    float wy = fy - (float)y0, wx = fx - (float)x0;
    const float* s = src + (size_t)bc * h * w;
    float top = s[(size_t)y0 * w + x0] * (1.f - wx) + s[(size_t)y0 * w + x1] * wx;
    float bot = s[(size_t)y1 * w + x0] * (1.f - wx) + s[(size_t)y1 * w + x1] * wx;
    dst[idx] = top * (1.f - wy) + bot * wy;
}

// ---------------- fully fused per-level loss kernel ----------------
// Block = TY x TX tile of pixels (grid exactly tiles the image; all levels divide).
// Computes: warped estimates (tile+halo, in smem), L1, LR-consistency, DSSIM
// (windows assigned to center pixel), edge-aware smoothness. No est buffers in DRAM.
__global__ __launch_bounds__(NT) void fused_level_kernel(
        const float* __restrict__ lp, const float* __restrict__ rp,
        const float* __restrict__ disp, int H, int W, double* accs) {
    __shared__ float s_dl[HN], s_dr[HN], s_xl[HN], s_xr[HN];
    __shared__ float s_Xl[HN], s_Xr[HN], s_El[HN], s_Er[HN];

    int b = blockIdx.z;
    int tx0 = blockIdx.x * TX, ty0 = blockIdx.y * TY;
    int hx0 = tx0 - 1, hy0 = ty0 - 1;
    int tid = threadIdx.x;
    int plane = H * W;
    const float* dl = disp + (size_t)b * 2 * plane;
    const float* dr = dl + plane;
    float scale = (float)(W - 1);

    // halo disparity + warp source coords
    for (int i = tid; i < HN; i += NT) {
        int hy = i / HTX, hx = i - (i / HTX) * HTX;
        int gy = hy0 + hy, gx = hx0 + hx;
        bool in = (gy >= 0) & (gy < H) & (gx >= 0) & (gx < W);
        float dlv = in ? __ldg(dl + gy * W + gx) : 0.f;
        float drv = in ? __ldg(dr + gy * W + gx) : 0.f;
        s_dl[i] = dlv; s_dr[i] = drv;
        s_xl[i] = (float)gx - dlv * scale;
        s_xr[i] = (float)gx + drv * scale;
    }
    __syncthreads();

    int ty = tid / TX, txx = tid - (tid / TX) * TX;
    int gy = ty0 + ty, gx = tx0 + txx;
    int ci = (ty + 1) * HTX + (txx + 1);

    float v[8] = {0.f,0.f,0.f,0.f,0.f,0.f,0.f,0.f};
    float gxl = 0.f, gyl = 0.f, gxr = 0.f, gyr = 0.f;
    bool win_valid = (gy >= 1) & (gy <= H - 2) & (gx >= 1) & (gx <= W - 2);
    bool xg = gx < W - 1, yg = gy < H - 1;
    const float inv9 = 1.f / 9.f;
    const float C1v = 1e-4f, C2v = 9e-4f;

    #pragma unroll
    for (int c = 0; c < 3; c++) {
        const float* L = lp + ((size_t)b * 3 + c) * plane;
        const float* R = rp + ((size_t)b * 3 + c) * plane;
        __syncthreads();  // prior-iteration reads done before overwrite
        for (int i = tid; i < HN; i += NT) {
            int hy = i / HTX, hx = i - (i / HTX) * HTX;
            int gy2 = hy0 + hy, gx2 = hx0 + hx;
            bool in = (gy2 >= 0) & (gy2 < H) & (gx2 >= 0) & (gx2 < W);
            float Xlv = 0.f, Xrv = 0.f, el = 0.f, er = 0.f;
            if (in) {
                const float* Lrow = L + (size_t)gy2 * W;
                const float* Rrow = R + (size_t)gy2 * W;
                Xlv = __ldg(Lrow + gx2);
                Xrv = __ldg(Rrow + gx2);
                float xl = s_xl[i];
                float fl = floorf(xl); int x0 = (int)fl; float wl = xl - fl;
                float a0 = (x0 >= 0 && x0 < W) ? __ldg(Rrow + x0) : 0.f;
                float a1 = (x0 + 1 >= 0 && x0 + 1 < W) ? __ldg(Rrow + x0 + 1) : 0.f;
                el = a0 * (1.f - wl) + a1 * wl;
                float xr = s_xr[i];
                float fr = floorf(xr); int x1 = (int)fr; float wr = xr - fr;
                float b0 = (x1 >= 0 && x1 < W) ? __ldg(Lrow + x1) : 0.f;
                float b1 = (x1 + 1 >= 0 && x1 + 1 < W) ? __ldg(Lrow + x1 + 1) : 0.f;
                er = b0 * (1.f - wr) + b1 * wr;
            }
            s_Xl[i] = Xlv; s_Xr[i] = Xrv;
            s_El[i] = el;  s_Er[i] = er;
        }
        __syncthreads();

        // L1 photometric at own pixel
        v[2] += fabsf(s_Xl[ci] - s_El[ci]);
        v[3] += fabsf(s_Xr[ci] - s_Er[ci]);
        // smoothness image-gradient weights (accumulate |grad| over channels)
        if (xg) { gxl += fabsf(s_Xl[ci] - s_Xl[ci + 1]);   gxr += fabsf(s_Xr[ci] - s_Xr[ci + 1]); }
        if (yg) { gyl += fabsf(s_Xl[ci] - s_Xl[ci + HTX]); gyr += fabsf(s_Xr[ci] - s_Xr[ci + HTX]); }
        // DSSIM window centered at own pixel
        if (win_valid) {
            float sx=0.f, sy=0.f, sxx=0.f, syy=0.f, sxy=0.f;
            float tx2=0.f, ty2=0.f, txx2=0.f, tyy2=0.f, txy2=0.f;
            #pragma unroll
            for (int j = -1; j <= 1; j++)
                #pragma unroll
                for (int i2 = -1; i2 <= 1; i2++) {
                    int p = ci + j * HTX + i2;
                    float a = s_Xl[p], e = s_El[p];
                    sx += a; sy += e; sxx += a*a; syy += e*e; sxy += a*e;
                    float ar = s_Xr[p], er2 = s_Er[p];
                    tx2 += ar; ty2 += er2; txx2 += ar*ar; tyy2 += er2*er2; txy2 += ar*er2;
                }
            {
                float mux = sx*inv9, muy = sy*inv9;
                float sigx = sxx*inv9 - mux*mux, sigy = syy*inv9 - muy*muy;
                float cov = sxy*inv9 - mux*muy;
                float ssim = ((2.f*mux*muy + C1v) * (2.f*cov + C2v))
                           / ((mux*mux + muy*muy + C1v) * (sigx + sigy + C2v));
                v[0] += fminf(fmaxf((1.f - ssim) * 0.5f, 0.f), 1.f);
            }
            {
                float mux = tx2*inv9, muy = ty2*inv9;
                float sigx = txx2*inv9 - mux*mux, sigy = tyy2*inv9 - muy*muy;
                float cov = txy2*inv9 - mux*muy;
                float ssim = ((2.f*mux*muy + C1v) * (2.f*cov + C2v))
                           / ((mux*mux + muy*muy + C1v) * (sigx + sigy + C2v));
                v[1] += fminf(fmaxf((1.f - ssim) * 0.5f, 0.f), 1.f);
            }
        }
    }

    // LR consistency at own pixel (gather disparity of other view)
    {
        const float* dlrow = dl + (size_t)gy * W;
        const float* drrow = dr + (size_t)gy * W;
        float xl = s_xl[ci];
        float fl = floorf(xl); int x0 = (int)fl; float wl = xl - fl;
        float a0 = (x0 >= 0 && x0 < W) ? __ldg(drrow + x0) : 0.f;
        float a1 = (x0 + 1 >= 0 && x0 + 1 < W) ? __ldg(drrow + x0 + 1) : 0.f;
        float r2l = a0 * (1.f - wl) + a1 * wl;
        float xr = s_xr[ci];
        float fr = floorf(xr); int x1 = (int)fr; float wr = xr - fr;
        float b0 = (x1 >= 0 && x1 < W) ? __ldg(dlrow + x1) : 0.f;
        float b1 = (x1 + 1 >= 0 && x1 + 1 < W) ? __ldg(dlrow + x1 + 1) : 0.f;
        float l2r = b0 * (1.f - wr) + b1 * wr;
        v[4] = fabsf(s_dl[ci] - r2l);
        v[5] = fabsf(s_dr[ci] - l2r);
    }

    // edge-aware smoothness
    {
        const float third = 1.f / 3.f;
        if (xg) {
            v[6] += fabsf((s_dl[ci] - s_dl[ci + 1]) * expf(-gxl * third));
            v[7] += fabsf((s_dr[ci] - s_dr[ci + 1]) * expf(-gxr * third));
        }
        if (yg) {
            v[6] += fabsf((s_dl[ci] - s_dl[ci + HTX]) * expf(-gyl * third));
            v[7] += fabsf((s_dr[ci] - s_dr[ci + HTX]) * expf(-gyr * third));
        }
    }

    block_accumulate<8>(v, accs);
}

// ---------------- final combine ----------------
__global__ void final_kernel(float* __restrict__ out) {
    double AP = 0.0, LR = 0.0, DS = 0.0;
    for (int i = 0; i < 4; i++) {
        int Hi = H0 >> i, Wi = W0 >> i;
        double Nd = (double)BB * 3.0 * (Hi - 2) * (Wi - 2);
        double Nl = (double)BB * 3.0 * Hi * Wi;
        double Np = (double)BB * Hi * Wi;
        const double* a = g_acc + i * 8;
        AP += 0.85 * (a[0] + a[1]) / Nd + 0.15 * (a[2] + a[3]) / Nl;
        LR += (a[4] + a[5]) / Np;
        DS += (a[6] + a[7]) / Np / (double)(1 << i);
    }
    AP *= 0.85;
    DS *= 0.1;
    double total = AP + LR + DS;
    out[0] = (float)total;
    out[1] = (float)AP;
    out[2] = (float)LR;
    out[3] = (float)DS;
}

// ---------------- host launcher ----------------
extern "C" void kernel_launch(void* const* d_in, const int* in_sizes, int n_in,
                              void* d_out, int out_size) {
    const float* disp0 = (const float*)d_in[0];
    const float* disp1 = (const float*)d_in[1];
    const float* disp2 = (const float*)d_in[2];
    const float* disp3 = (const float*)d_in[3];
    const float* left  = (const float*)d_in[4];
    const float* right = (const float*)d_in[5];
    float* out = (float*)d_out;

    static bool init = false;
    static float *lp1, *rp1, *lp2, *rp2, *lp3, *rp3;
    static double* acc;
    if (!init) {
        cudaGetSymbolAddress((void**)&lp1, g_lp1);
        cudaGetSymbolAddress((void**)&rp1, g_rp1);
        cudaGetSymbolAddress((void**)&lp2, g_lp2);
        cudaGetSymbolAddress((void**)&rp2, g_rp2);
        cudaGetSymbolAddress((void**)&lp3, g_lp3);
        cudaGetSymbolAddress((void**)&rp3, g_rp3);
        cudaGetSymbolAddress((void**)&acc, g_acc);
        init = true;
    }

    zero_acc_kernel<<<1, 32>>>();

    const int BC = BB * 3;
    {
        int n1 = BC * 128 * 256;
        resize2_kernel<<<(2*n1 + NT - 1) / NT, NT>>>(left, lp1, right, rp1, BC, 256, 512, 128, 256);
        int n2 = BC * 64 * 128;
        resize2_kernel<<<(2*n2 + NT - 1) / NT, NT>>>(lp1, lp2, rp1, rp2, BC, 128, 256, 64, 128);
        int n3 = BC * 32 * 64;
        resize2_kernel<<<(2*n3 + NT - 1) / NT, NT>>>(lp2, lp3, rp2, rp3, BC, 64, 128, 32, 64);
    }

    const float* lps[4]   = {left,  lp1, lp2, lp3};
    const float* rps[4]   = {right, rp1, rp2, rp3};
    const float* disps[4] = {disp0, disp1, disp2, disp3};
    int Hs[4] = {256, 128, 64, 32};
    int Ws[4] = {512, 256, 128, 64};

    for (int i = 0; i < 4; i++) {
        int H = Hs[i], W = Ws[i];
        dim3 grid(W / TX, H / TY, BB);
        fused_level_kernel<<<grid, NT>>>(lps[i], rps[i], disps[i], H, W, acc + i * 8);
    }

    final_kernel<<<1, 1>>>(out);
}

// round 4
// speedup vs baseline: 1.3727x; 1.2249x over previous
#include <cuda_runtime.h>
#include <math.h>

#define BB 32
#define H0 256
#define W0 512
#define NT 256

#define TX 32
#define TY 8
#define HTX (TX + 2)
#define HTY (TY + 2)
#define HN (HTX * HTY)

// ---------------- scratch ----------------
__device__ float g_lp1[BB*3*128*256];
__device__ float g_rp1[BB*3*128*256];
__device__ float g_lp2[BB*3*64*128];
__device__ float g_rp2[BB*3*64*128];
__device__ float g_lp3[BB*3*32*64];
__device__ float g_rp3[BB*3*32*64];

// per level i, 8 slots: 0 dssim_l, 1 dssim_r, 2 l1_l, 3 l1_r, 4 lr_l, 5 lr_r, 6 ds_l, 7 ds_r
__device__ double g_acc[32];

// ---------------- reduction helper ----------------
template<int NV>
__device__ __forceinline__ void block_accumulate(float (&v)[NV], double* accs) {
    #pragma unroll
    for (int k = 0; k < NV; k++)
        #pragma unroll
        for (int o = 16; o > 0; o >>= 1)
            v[k] += __shfl_down_sync(0xffffffffu, v[k], o);
    __shared__ float sh[NV][8];
    int lane = threadIdx.x & 31, w = threadIdx.x >> 5;
    if (lane == 0) {
        #pragma unroll
        for (int k = 0; k < NV; k++) sh[k][w] = v[k];
    }
    __syncthreads();
    if (threadIdx.x == 0) {
        int nw = (blockDim.x + 31) >> 5;
        #pragma unroll
        for (int k = 0; k < NV; k++) {
            float s = 0.f;
            for (int i = 0; i < nw; i++) s += sh[k][i];
            atomicAdd(accs + k, (double)s);
        }
    }
}

__global__ void zero_acc_kernel() {
    if (threadIdx.x < 32) g_acc[threadIdx.x] = 0.0;
}

// ---------------- paired bilinear align-corners resize ----------------
__global__ void resize2_kernel(const float* __restrict__ srcA, float* __restrict__ dstA,
                               const float* __restrict__ srcB, float* __restrict__ dstB,
                               int BC, int h, int w, int nh, int nw) {
    int idx = blockIdx.x * blockDim.x + threadIdx.x;
    int total = BC * nh * nw;
    int which = 0;
    if (idx >= total) { idx -= total; which = 1; if (idx >= total) return; }
    const float* src = which ? srcB : srcA;
    float* dst = which ? dstB : dstA;
    int x  = idx % nw;
    int t  = idx / nw;
    int y  = t % nh;
    int bc = t / nh;
    float fy = (float)y * (float)(h - 1) / (float)(nh - 1);
    float fx = (float)x * (float)(w - 1) / (float)(nw - 1);
    int y0 = (int)floorf(fy); int y1 = min(y0 + 1, h - 1);
    int x0 = (int)floorf(fx); int x1 = min(x0 + 1, w - 1);
    float wy = fy - (float)y0, wx = fx - (float)x0;
    const float* s = src + (size_t)bc * h * w;
    float top = s[(size_t)y0 * w + x0] * (1.f - wx) + s[(size_t)y0 * w + x1] * wx;
    float bot = s[(size_t)y1 * w + x0] * (1.f - wx) + s[(size_t)y1 * w + x1] * wx;
    dst[idx] = top * (1.f - wy) + bot * wy;
}

// ---------------- all-level fused loss kernel ----------------
struct LevelArgs {
    const float* lp[4];
    const float* rp[4];
    const float* disp[4];
};

// Blocks per level: (H/TY)*BB = {1024, 512, 256, 128}; prefix {0,1024,1536,1792}.
// Each block = one 8-row strip of one batch image; loops over W/TX x-tiles,
// accumulating all 8 loss terms in registers; ONE atomic set per block.
__global__ __launch_bounds__(NT) void fused_all_kernel(LevelArgs args) {
    __shared__ float s_dl[HN], s_dr[HN], s_xl[HN], s_xr[HN];
    __shared__ float s_Xl[HN], s_Xr[HN], s_El[HN], s_Er[HN];

    int bid = blockIdx.x;
    int lvl, lbid;
    if (bid < 1024)      { lvl = 0; lbid = bid; }
    else if (bid < 1536) { lvl = 1; lbid = bid - 1024; }
    else if (bid < 1792) { lvl = 2; lbid = bid - 1536; }
    else                 { lvl = 3; lbid = bid - 1792; }
    int H = H0 >> lvl, W = W0 >> lvl;
    int n_strips = H / TY;
    int b  = lbid / n_strips;
    int ys = lbid - b * n_strips;
    int ty0 = ys * TY;
    int ntx = W / TX;

    const float* lp = args.lp[lvl];
    const float* rp = args.rp[lvl];
    int plane = H * W;
    const float* dl = args.disp[lvl] + (size_t)b * 2 * plane;
    const float* dr = dl + plane;
    double* accs = g_acc + lvl * 8;

    int tid = threadIdx.x;
    int ty = tid / TX, txl = tid - (tid / TX) * TX;
    int gy = ty0 + ty;
    int ci = (ty + 1) * HTX + (txl + 1);
    int hy0 = ty0 - 1;
    float scale = (float)(W - 1);
    const float inv9 = 1.f / 9.f;
    const float C1v = 1e-4f, C2v = 9e-4f;
    const float third = 1.f / 3.f;
    bool ygood = gy < H - 1;
    bool wy_ok = (gy >= 1) & (gy <= H - 2);

    float v[8] = {0.f,0.f,0.f,0.f,0.f,0.f,0.f,0.f};

    for (int t = 0; t < ntx; t++) {
        int tx0 = t * TX;
        int hx0 = tx0 - 1;
        int gx = tx0 + txl;
        bool xgood = gx < W - 1;
        bool win_valid = wy_ok & (gx >= 1) & (gx <= W - 2);

        __syncthreads();  // previous tile's smem reads complete
        for (int i = tid; i < HN; i += NT) {
            int hy = i / HTX, hx = i - (i / HTX) * HTX;
            int gy2 = hy0 + hy, gx2 = hx0 + hx;
            bool in = (gy2 >= 0) & (gy2 < H) & (gx2 >= 0) & (gx2 < W);
            float dlv = in ? __ldg(dl + gy2 * W + gx2) : 0.f;
            float drv = in ? __ldg(dr + gy2 * W + gx2) : 0.f;
            s_dl[i] = dlv; s_dr[i] = drv;
            s_xl[i] = (float)gx2 - dlv * scale;
            s_xr[i] = (float)gx2 + drv * scale;
        }
        __syncthreads();

        float gxl = 0.f, gyl = 0.f, gxr = 0.f, gyr = 0.f;

        #pragma unroll
        for (int c = 0; c < 3; c++) {
            const float* L = lp + ((size_t)b * 3 + c) * plane;
            const float* R = rp + ((size_t)b * 3 + c) * plane;
            __syncthreads();  // prior channel's smem reads complete
            for (int i = tid; i < HN; i += NT) {
                int hy = i / HTX, hx = i - (i / HTX) * HTX;
                int gy2 = hy0 + hy, gx2 = hx0 + hx;
                bool in = (gy2 >= 0) & (gy2 < H) & (gx2 >= 0) & (gx2 < W);
                float Xlv = 0.f, Xrv = 0.f, el = 0.f, er = 0.f;
                if (in) {
                    const float* Lrow = L + (size_t)gy2 * W;
                    const float* Rrow = R + (size_t)gy2 * W;
                    Xlv = __ldg(Lrow + gx2);
                    Xrv = __ldg(Rrow + gx2);
                    float xl = s_xl[i];
                    float fl = floorf(xl); int x0 = (int)fl; float wl = xl - fl;
                    float a0 = (x0 >= 0 && x0 < W) ? __ldg(Rrow + x0) : 0.f;
                    float a1 = (x0 + 1 >= 0 && x0 + 1 < W) ? __ldg(Rrow + x0 + 1) : 0.f;
                    el = a0 * (1.f - wl) + a1 * wl;
                    float xr = s_xr[i];
                    float fr = floorf(xr); int x1 = (int)fr; float wr = xr - fr;
                    float b0 = (x1 >= 0 && x1 < W) ? __ldg(Lrow + x1) : 0.f;
                    float b1 = (x1 + 1 >= 0 && x1 + 1 < W) ? __ldg(Lrow + x1 + 1) : 0.f;
                    er = b0 * (1.f - wr) + b1 * wr;
                }
                s_Xl[i] = Xlv; s_Xr[i] = Xrv;
                s_El[i] = el;  s_Er[i] = er;
            }
            __syncthreads();

            v[2] += fabsf(s_Xl[ci] - s_El[ci]);
            v[3] += fabsf(s_Xr[ci] - s_Er[ci]);
            if (xgood) { gxl += fabsf(s_Xl[ci] - s_Xl[ci + 1]);   gxr += fabsf(s_Xr[ci] - s_Xr[ci + 1]); }
            if (ygood) { gyl += fabsf(s_Xl[ci] - s_Xl[ci + HTX]); gyr += fabsf(s_Xr[ci] - s_Xr[ci + HTX]); }
            if (win_valid) {
                float sx=0.f, sy=0.f, sxx=0.f, syy=0.f, sxy=0.f;
                float tx2=0.f, ty2=0.f, txx2=0.f, tyy2=0.f, txy2=0.f;
                #pragma unroll
                for (int j = -1; j <= 1; j++)
                    #pragma unroll
                    for (int i2 = -1; i2 <= 1; i2++) {
                        int p = ci + j * HTX + i2;
                        float a = s_Xl[p], e = s_El[p];
                        sx += a; sy += e; sxx += a*a; syy += e*e; sxy += a*e;
                        float ar = s_Xr[p], er2 = s_Er[p];
                        tx2 += ar; ty2 += er2; txx2 += ar*ar; tyy2 += er2*er2; txy2 += ar*er2;
                    }
                {
                    float mux = sx*inv9, muy = sy*inv9;
                    float sigx = sxx*inv9 - mux*mux, sigy = syy*inv9 - muy*muy;
                    float cov = sxy*inv9 - mux*muy;
                    float ssim = ((2.f*mux*muy + C1v) * (2.f*cov + C2v))
                               / ((mux*mux + muy*muy + C1v) * (sigx + sigy + C2v));
                    v[0] += fminf(fmaxf((1.f - ssim) * 0.5f, 0.f), 1.f);
                }
                {
                    float mux = tx2*inv9, muy = ty2*inv9;
                    float sigx = txx2*inv9 - mux*mux, sigy = tyy2*inv9 - muy*muy;
                    float cov = txy2*inv9 - mux*muy;
                    float ssim = ((2.f*mux*muy + C1v) * (2.f*cov + C2v))
                               / ((mux*mux + muy*muy + C1v) * (sigx + sigy + C2v));
                    v[1] += fminf(fmaxf((1.f - ssim) * 0.5f, 0.f), 1.f);
                }
            }
        }

        // LR consistency at own pixel
        {
            const float* dlrow = dl + (size_t)gy * W;
            const float* drrow = dr + (size_t)gy * W;
            float xl = s_xl[ci];
            float fl = floorf(xl); int x0 = (int)fl; float wl = xl - fl;
            float a0 = (x0 >= 0 && x0 < W) ? __ldg(drrow + x0) : 0.f;
            float a1 = (x0 + 1 >= 0 && x0 + 1 < W) ? __ldg(drrow + x0 + 1) : 0.f;
            float r2l = a0 * (1.f - wl) + a1 * wl;
            float xr = s_xr[ci];
            float fr = floorf(xr); int x1 = (int)fr; float wr = xr - fr;
            float b0 = (x1 >= 0 && x1 < W) ? __ldg(dlrow + x1) : 0.f;
            float b1 = (x1 + 1 >= 0 && x1 + 1 < W) ? __ldg(dlrow + x1 + 1) : 0.f;
            float l2r = b0 * (1.f - wr) + b1 * wr;
            v[4] += fabsf(s_dl[ci] - r2l);
            v[5] += fabsf(s_dr[ci] - l2r);
        }

        // edge-aware smoothness
        if (xgood) {
            v[6] += fabsf((s_dl[ci] - s_dl[ci + 1]) * expf(-gxl * third));
            v[7] += fabsf((s_dr[ci] - s_dr[ci + 1]) * expf(-gxr * third));
        }
        if (ygood) {
            v[6] += fabsf((s_dl[ci] - s_dl[ci + HTX]) * expf(-gyl * third));
            v[7] += fabsf((s_dr[ci] - s_dr[ci + HTX]) * expf(-gyr * third));
        }
    }

    block_accumulate<8>(v, accs);
}

// ---------------- final combine ----------------
__global__ void final_kernel(float* __restrict__ out) {
    double AP = 0.0, LR = 0.0, DS = 0.0;
    for (int i = 0; i < 4; i++) {
        int Hi = H0 >> i, Wi = W0 >> i;
        double Nd = (double)BB * 3.0 * (Hi - 2) * (Wi - 2);
        double Nl = (double)BB * 3.0 * Hi * Wi;
        double Np = (double)BB * Hi * Wi;
        const double* a = g_acc + i * 8;
        AP += 0.85 * (a[0] + a[1]) / Nd + 0.15 * (a[2] + a[3]) / Nl;
        LR += (a[4] + a[5]) / Np;
        DS += (a[6] + a[7]) / Np / (double)(1 << i);
    }
    AP *= 0.85;
    DS *= 0.1;
    double total = AP + LR + DS;
    out[0] = (float)total;
    out[1] = (float)AP;
    out[2] = (float)LR;
    out[3] = (float)DS;
}

// ---------------- host launcher ----------------
extern "C" void kernel_launch(void* const* d_in, const int* in_sizes, int n_in,
                              void* d_out, int out_size) {
    const float* disp0 = (const float*)d_in[0];
    const float* disp1 = (const float*)d_in[1];
    const float* disp2 = (const float*)d_in[2];
    const float* disp3 = (const float*)d_in[3];
    const float* left  = (const float*)d_in[4];
    const float* right = (const float*)d_in[5];
    float* out = (float*)d_out;

    static bool init = false;
    static float *lp1, *rp1, *lp2, *rp2, *lp3, *rp3;
    if (!init) {
        cudaGetSymbolAddress((void**)&lp1, g_lp1);
        cudaGetSymbolAddress((void**)&rp1, g_rp1);
        cudaGetSymbolAddress((void**)&lp2, g_lp2);
        cudaGetSymbolAddress((void**)&rp2, g_rp2);
        cudaGetSymbolAddress((void**)&lp3, g_lp3);
        cudaGetSymbolAddress((void**)&rp3, g_rp3);
        init = true;
    }

    zero_acc_kernel<<<1, 32>>>();

    const int BC = BB * 3;
    {
        int n1 = BC * 128 * 256;
        resize2_kernel<<<(2*n1 + NT - 1) / NT, NT>>>(left, lp1, right, rp1, BC, 256, 512, 128, 256);
        int n2 = BC * 64 * 128;
        resize2_kernel<<<(2*n2 + NT - 1) / NT, NT>>>(lp1, lp2, rp1, rp2, BC, 128, 256, 64, 128);
        int n3 = BC * 32 * 64;
        resize2_kernel<<<(2*n3 + NT - 1) / NT, NT>>>(lp2, lp3, rp2, rp3, BC, 64, 128, 32, 64);
    }

    LevelArgs args;
    args.lp[0] = left;  args.lp[1] = lp1; args.lp[2] = lp2; args.lp[3] = lp3;
    args.rp[0] = right; args.rp[1] = rp1; args.rp[2] = rp2; args.rp[3] = rp3;
    args.disp[0] = disp0; args.disp[1] = disp1; args.disp[2] = disp2; args.disp[3] = disp3;

    fused_all_kernel<<<1920, NT>>>(args);

    final_kernel<<<1, 1>>>(out);
}

// round 5
// speedup vs baseline: 1.5014x; 1.0937x over previous
#include <cuda_runtime.h>
#include <math.h>

#define BB 32
#define H0 256
#define W0 512
#define NT 128            // 4 warps per block
#define FULLMASK 0xffffffffu

// warp-slot layout: per warp = (level, batch, 30-column slot, 64-row chunk)
// L0: 18 xslots * 4 chunks * 32 b = 2304 ; L1: 9*2*32 = 576 ; L2: 5*1*32 = 160 ; L3: 3*1*32 = 96
#define L1_BASE 2304
#define L2_BASE 2880
#define L3_BASE 3040
#define TOTAL_WARPS 3136
#define NBLOCKS (TOTAL_WARPS / 4)   // 784 ; all level boundaries divisible by 4

// ---------------- scratch ----------------
__device__ float g_lp1[BB*3*128*256];
__device__ float g_rp1[BB*3*128*256];
__device__ float g_lp2[BB*3*64*128];
__device__ float g_rp2[BB*3*64*128];
__device__ float g_lp3[BB*3*32*64];
__device__ float g_rp3[BB*3*32*64];

// per level i, 8 slots: 0 dssim_l, 1 dssim_r, 2 l1_l, 3 l1_r, 4 lr_l, 5 lr_r, 6 ds_l, 7 ds_r
__device__ double g_acc[32];

// ---------------- reduction helper ----------------
template<int NV>
__device__ __forceinline__ void block_accumulate(float (&v)[NV], double* accs) {
    #pragma unroll
    for (int k = 0; k < NV; k++)
        #pragma unroll
        for (int o = 16; o > 0; o >>= 1)
            v[k] += __shfl_down_sync(FULLMASK, v[k], o);
    __shared__ float sh[NV][4];
    int lane = threadIdx.x & 31, w = threadIdx.x >> 5;
    if (lane == 0) {
        #pragma unroll
        for (int k = 0; k < NV; k++) sh[k][w] = v[k];
    }
    __syncthreads();
    if (threadIdx.x == 0) {
        #pragma unroll
        for (int k = 0; k < NV; k++) {
            float s = sh[k][0] + sh[k][1] + sh[k][2] + sh[k][3];
            atomicAdd(accs + k, (double)s);
        }
    }
}

__global__ void zero_acc_kernel() {
    if (threadIdx.x < 32) g_acc[threadIdx.x] = 0.0;
}

// ---------------- paired bilinear align-corners resize ----------------
__global__ void resize2_kernel(const float* __restrict__ srcA, float* __restrict__ dstA,
                               const float* __restrict__ srcB, float* __restrict__ dstB,
                               int BC, int h, int w, int nh, int nw) {
    int idx = blockIdx.x * blockDim.x + threadIdx.x;
    int total = BC * nh * nw;
    int which = 0;
    if (idx >= total) { idx -= total; which = 1; if (idx >= total) return; }
    const float* src = which ? srcB : srcA;
    float* dst = which ? dstB : dstA;
    int x  = idx % nw;
    int t  = idx / nw;
    int y  = t % nh;
    int bc = t / nh;
    float fy = (float)y * (float)(h - 1) / (float)(nh - 1);
    float fx = (float)x * (float)(w - 1) / (float)(nw - 1);
    int y0 = (int)floorf(fy); int y1 = min(y0 + 1, h - 1);
    int x0 = (int)floorf(fx); int x1 = min(x0 + 1, w - 1);
    float wy = fy - (float)y0, wx = fx - (float)x0;
    const float* s = src + (size_t)bc * h * w;
    float top = s[(size_t)y0 * w + x0] * (1.f - wx) + s[(size_t)y0 * w + x1] * wx;
    float bot = s[(size_t)y1 * w + x0] * (1.f - wx) + s[(size_t)y1 * w + x1] * wx;
    dst[idx] = top * (1.f - wy) + bot * wy;
}

// ---------------- register sliding-window fused loss ----------------
struct LevelArgs {
    const float* lp[4];
    const float* rp[4];
    const float* disp[4];
};

__global__ __launch_bounds__(NT) void fused_all_kernel(LevelArgs args) {
    int lane = threadIdx.x & 31;
    int g = blockIdx.x * (NT / 32) + (threadIdx.x >> 5);

    int lvl, base, wpi, nx, W, H, CH;
    if (g < L1_BASE)      { lvl = 0; base = 0;       wpi = 72; nx = 18; W = 512; H = 256; CH = 64; }
    else if (g < L2_BASE) { lvl = 1; base = L1_BASE; wpi = 18; nx = 9;  W = 256; H = 128; CH = 64; }
    else if (g < L3_BASE) { lvl = 2; base = L2_BASE; wpi = 5;  nx = 5;  W = 128; H = 64;  CH = 64; }
    else                  { lvl = 3; base = L3_BASE; wpi = 3;  nx = 3;  W = 64;  H = 32;  CH = 32; }

    int r   = g - base;
    int b   = r / wpi;
    int rr  = r - b * wpi;
    int xsl = rr % nx;
    int ych = rr / nx;
    int y0  = ych * CH;
    int x   = xsl * 30 + lane - 1;

    const float* lp = args.lp[lvl];
    const float* rp = args.rp[lvl];
    int plane = H * W;
    const float* dlp = args.disp[lvl] + (size_t)b * 2 * plane;
    const float* drp = dlp + plane;
    float scale = (float)(W - 1);
    bool inx = (x >= 0) & (x < W);
    bool lane_emit = (lane >= 1) & (lane <= 30) & (x < W);
    bool dss_x = lane_emit & (x >= 1) & (x <= W - 2);

    int ys = max(y0 - 2, 0);
    int ye = min(y0 + CH, H - 1);

    const float* dlrow = dlp + (size_t)ys * W;
    const float* drrow = drp + (size_t)ys * W;
    const float* Lrow[3];
    const float* Rrow[3];
    #pragma unroll
    for (int c = 0; c < 3; c++) {
        Lrow[c] = lp + ((size_t)b * 3 + c) * plane + (size_t)ys * W;
        Rrow[c] = rp + ((size_t)b * 3 + c) * plane + (size_t)ys * W;
    }

    float s2[3][10], s1[3][10];
    #pragma unroll
    for (int c = 0; c < 3; c++)
        #pragma unroll
        for (int k = 0; k < 10; k++) { s2[c][k] = 0.f; s1[c][k] = 0.f; }
    float pXl[3] = {0.f,0.f,0.f}, pXr[3] = {0.f,0.f,0.f};
    float pdl = 0.f, pdr = 0.f;

    float v[8] = {0.f,0.f,0.f,0.f,0.f,0.f,0.f,0.f};
    const float inv9 = 1.f / 9.f;
    const float C1v = 1e-4f, C2v = 9e-4f, third = 1.f / 3.f;

    for (int y = ys; y <= ye; y++) {
        // ----- disparity row + warp coordinates -----
        float dlv = inx ? __ldg(dlrow + x) : 0.f;
        float drv = inx ? __ldg(drrow + x) : 0.f;
        float xlf = (float)x - dlv * scale;
        float xrf = (float)x + drv * scale;
        float fl = floorf(xlf); int xl0 = (int)fl; float wl = xlf - fl;
        float fr = floorf(xrf); int xr0 = (int)fr; float wr = xrf - fr;
        bool l0v = (xl0 >= 0) & (xl0 < W);
        bool l1v = (xl0 >= -1) & (xl0 < W - 1);
        bool r0v = (xr0 >= 0) & (xr0 < W);
        bool r1v = (xr0 >= -1) & (xr0 < W - 1);

        // LR-consistency gathers
        float r2l = (l0v ? __ldg(drrow + xl0) : 0.f) * (1.f - wl)
                  + (l1v ? __ldg(drrow + xl0 + 1) : 0.f) * wl;
        float l2r = (r0v ? __ldg(dlrow + xr0) : 0.f) * (1.f - wr)
                  + (r1v ? __ldg(dlrow + xr0 + 1) : 0.f) * wr;
        float ndl = __shfl_down_sync(FULLMASK, dlv, 1);
        float ndr = __shfl_down_sync(FULLMASK, drv, 1);

        // ----- per-channel values, products, horizontal 3-sums -----
        float Xl[3], Xr[3], El[3], Er[3], nXl[3], nXr[3], hs[3][10];
        #pragma unroll
        for (int c = 0; c < 3; c++) {
            float a  = inx ? __ldg(Lrow[c] + x) : 0.f;
            float ar = inx ? __ldg(Rrow[c] + x) : 0.f;
            float e  = (l0v ? __ldg(Rrow[c] + xl0) : 0.f) * (1.f - wl)
                     + (l1v ? __ldg(Rrow[c] + xl0 + 1) : 0.f) * wl;
            float er = (r0v ? __ldg(Lrow[c] + xr0) : 0.f) * (1.f - wr)
                     + (r1v ? __ldg(Lrow[c] + xr0 + 1) : 0.f) * wr;
            Xl[c] = a; Xr[c] = ar; El[c] = e; Er[c] = er;
            nXl[c] = __shfl_down_sync(FULLMASK, a, 1);
            nXr[c] = __shfl_down_sync(FULLMASK, ar, 1);
            float q[10];
            q[0] = a;  q[1] = e;  q[2] = a * a;   q[3] = e * e;   q[4] = a * e;
            q[5] = ar; q[6] = er; q[7] = ar * ar; q[8] = er * er; q[9] = ar * er;
            #pragma unroll
            for (int k = 0; k < 10; k++)
                hs[c][k] = __shfl_up_sync(FULLMASK, q[k], 1) + q[k]
                         + __shfl_down_sync(FULLMASK, q[k], 1);
        }

        bool own  = (y >= y0) & (y < y0 + CH);
        bool ownp = (y - 1 >= y0) & (y - 1 < y0 + CH);

        if (lane_emit) {
            if (own) {
                #pragma unroll
                for (int c = 0; c < 3; c++) {
                    v[2] += fabsf(Xl[c] - El[c]);
                    v[3] += fabsf(Xr[c] - Er[c]);
                }
                v[4] += fabsf(dlv - r2l);
                v[5] += fabsf(drv - l2r);
                if (x < W - 1) {
                    float gxl = fabsf(Xl[0]-nXl[0]) + fabsf(Xl[1]-nXl[1]) + fabsf(Xl[2]-nXl[2]);
                    float gxr = fabsf(Xr[0]-nXr[0]) + fabsf(Xr[1]-nXr[1]) + fabsf(Xr[2]-nXr[2]);
                    v[6] += fabsf((dlv - ndl) * __expf(-gxl * third));
                    v[7] += fabsf((drv - ndr) * __expf(-gxr * third));
                }
            }
            if (ownp) {
                // y-smoothness for row y-1 (last row's y-grad is defined 0, never emitted)
                float gyl = fabsf(pXl[0]-Xl[0]) + fabsf(pXl[1]-Xl[1]) + fabsf(pXl[2]-Xl[2]);
                float gyr = fabsf(pXr[0]-Xr[0]) + fabsf(pXr[1]-Xr[1]) + fabsf(pXr[2]-Xr[2]);
                v[6] += fabsf((pdl - dlv) * __expf(-gyl * third));
                v[7] += fabsf((pdr - drv) * __expf(-gyr * third));
            }
            if (ownp & (y - 1 >= 1) & (y - 1 <= H - 2) & dss_x) {
                // DSSIM window centered at (y-1, x): vertical sum = s2 + hs(current)
                #pragma unroll
                for (int c = 0; c < 3; c++) {
                    float Sa  = s2[c][0] + hs[c][0];
                    float Se  = s2[c][1] + hs[c][1];
                    float Saa = s2[c][2] + hs[c][2];
                    float See = s2[c][3] + hs[c][3];
                    float Sae = s2[c][4] + hs[c][4];
                    float mux = Sa * inv9, muy = Se * inv9;
                    float sigx = Saa * inv9 - mux * mux;
                    float sigy = See * inv9 - muy * muy;
                    float cov  = Sae * inv9 - mux * muy;
                    float ssim = __fdividef((2.f*mux*muy + C1v) * (2.f*cov + C2v),
                                            (mux*mux + muy*muy + C1v) * (sigx + sigy + C2v));
                    v[0] += fminf(fmaxf((1.f - ssim) * 0.5f, 0.f), 1.f);

                    float Ta  = s2[c][5] + hs[c][5];
                    float Te  = s2[c][6] + hs[c][6];
                    float Taa = s2[c][7] + hs[c][7];
                    float Tee = s2[c][8] + hs[c][8];
                    float Tae = s2[c][9] + hs[c][9];
                    float mux2 = Ta * inv9, muy2 = Te * inv9;
                    float sigx2 = Taa * inv9 - mux2 * mux2;
                    float sigy2 = Tee * inv9 - muy2 * muy2;
                    float cov2  = Tae * inv9 - mux2 * muy2;
                    float ssim2 = __fdividef((2.f*mux2*muy2 + C1v) * (2.f*cov2 + C2v),
                                             (mux2*mux2 + muy2*muy2 + C1v) * (sigx2 + sigy2 + C2v));
                    v[1] += fminf(fmaxf((1.f - ssim2) * 0.5f, 0.f), 1.f);
                }
            }
        }

        // ----- rotate vertical ring + prev-row state -----
        #pragma unroll
        for (int c = 0; c < 3; c++)
            #pragma unroll
            for (int k = 0; k < 10; k++) {
                float t = hs[c][k];
                s2[c][k] = s1[c][k] + t;
                s1[c][k] = t;
            }
        #pragma unroll
        for (int c = 0; c < 3; c++) { pXl[c] = Xl[c]; pXr[c] = Xr[c]; }
        pdl = dlv; pdr = drv;

        dlrow += W; drrow += W;
        #pragma unroll
        for (int c = 0; c < 3; c++) { Lrow[c] += W; Rrow[c] += W; }
    }

    block_accumulate<8>(v, g_acc + lvl * 8);
}

// ---------------- final combine ----------------
__global__ void final_kernel(float* __restrict__ out) {
    double AP = 0.0, LR = 0.0, DS = 0.0;
    for (int i = 0; i < 4; i++) {
        int Hi = H0 >> i, Wi = W0 >> i;
        double Nd = (double)BB * 3.0 * (Hi - 2) * (Wi - 2);
        double Nl = (double)BB * 3.0 * Hi * Wi;
        double Np = (double)BB * Hi * Wi;
        const double* a = g_acc + i * 8;
        AP += 0.85 * (a[0] + a[1]) / Nd + 0.15 * (a[2] + a[3]) / Nl;
        LR += (a[4] + a[5]) / Np;
        DS += (a[6] + a[7]) / Np / (double)(1 << i);
    }
    AP *= 0.85;
    DS *= 0.1;
    double total = AP + LR + DS;
    out[0] = (float)total;
    out[1] = (float)AP;
    out[2] = (float)LR;
    out[3] = (float)DS;
}

// ---------------- host launcher ----------------
extern "C" void kernel_launch(void* const* d_in, const int* in_sizes, int n_in,
                              void* d_out, int out_size) {
    const float* disp0 = (const float*)d_in[0];
    const float* disp1 = (const float*)d_in[1];
    const float* disp2 = (const float*)d_in[2];
    const float* disp3 = (const float*)d_in[3];
    const float* left  = (const float*)d_in[4];
    const float* right = (const float*)d_in[5];
    float* out = (float*)d_out;

    static bool init = false;
    static float *lp1, *rp1, *lp2, *rp2, *lp3, *rp3;
    if (!init) {
        cudaGetSymbolAddress((void**)&lp1, g_lp1);
        cudaGetSymbolAddress((void**)&rp1, g_rp1);
        cudaGetSymbolAddress((void**)&lp2, g_lp2);
        cudaGetSymbolAddress((void**)&rp2, g_rp2);
        cudaGetSymbolAddress((void**)&lp3, g_lp3);
        cudaGetSymbolAddress((void**)&rp3, g_rp3);
        init = true;
    }

    zero_acc_kernel<<<1, 32>>>();

    const int BC = BB * 3;
    {
        int n1 = BC * 128 * 256;
        resize2_kernel<<<(2*n1 + 255) / 256, 256>>>(left, lp1, right, rp1, BC, 256, 512, 128, 256);
        int n2 = BC * 64 * 128;
        resize2_kernel<<<(2*n2 + 255) / 256, 256>>>(lp1, lp2, rp1, rp2, BC, 128, 256, 64, 128);
        int n3 = BC * 32 * 64;
        resize2_kernel<<<(2*n3 + 255) / 256, 256>>>(lp2, lp3, rp2, rp3, BC, 64, 128, 32, 64);
    }

    LevelArgs args;
    args.lp[0] = left;  args.lp[1] = lp1; args.lp[2] = lp2; args.lp[3] = lp3;
    args.rp[0] = right; args.rp[1] = rp1; args.rp[2] = rp2; args.rp[3] = rp3;
    args.disp[0] = disp0; args.disp[1] = disp1; args.disp[2] = disp2; args.disp[3] = disp3;

    fused_all_kernel<<<NBLOCKS, NT>>>(args);

    final_kernel<<<1, 1>>>(out);
}